// round 13
// baseline (speedup 1.0000x reference)
#include <cuda_runtime.h>
#include <cuda_bf16.h>

#define BB 16
#define TT 512
#define DD 384
#define D4 96             // float4 per row
#define MAXLEN 4096
#define ROWS 32           // mel rows per block (8 per warp)
#define CHUNKS (MAXLEN / ROWS)   // 128
#define NTHR 128

__global__ void __launch_bounds__(NTHR, 16)
fused_kernel(const int* __restrict__ dur,
             const float4* __restrict__ enc,
             float4* __restrict__ out,
             float* __restrict__ mel_out, int write_mel)
{
    __shared__ int s_cum[TT];
    __shared__ int s_wsum[4];

    const int bidx  = blockIdx.x;
    const int b     = bidx >> 7;             // / CHUNKS
    const int chunk = bidx & (CHUNKS - 1);
    const int tid   = threadIdx.x;
    const int lane  = tid & 31;
    const int wid   = tid >> 5;
    const unsigned FULL = 0xffffffffu;

    // ---------- Phase 1: cumsum of 512 durations (4 per thread, int4) ------
    int4 dd = ((const int4*)(dur + b * TT))[tid];
    int v = dd.x + dd.y + dd.z + dd.w;
    #pragma unroll
    for (int off = 1; off < 32; off <<= 1) {
        int n = __shfl_up_sync(FULL, v, off);
        if (lane >= off) v += n;
    }
    if (lane == 31) s_wsum[wid] = v;
    __syncthreads();
    if (wid == 0 && lane < 4) {
        int w = s_wsum[lane];
        #pragma unroll
        for (int off = 1; off < 4; off <<= 1) {
            int n = __shfl_up_sync(0x0000000fu, w, off);
            if (lane >= off) w += n;
        }
        s_wsum[lane] = w;
    }
    __syncthreads();
    const int base = (wid > 0) ? s_wsum[wid - 1] : 0;
    const int c3 = v + base;                 // inclusive at 4th element
    const int c2 = c3 - dd.w;
    const int c1 = c2 - dd.z;
    const int c0 = c1 - dd.y;
    s_cum[4 * tid + 0] = c0;
    s_cum[4 * tid + 1] = c1;
    s_cum[4 * tid + 2] = c2;
    s_cum[4 * tid + 3] = c3;
    __syncthreads();

    const int mel  = s_cum[TT - 1];
    const int lim  = (mel < MAXLEN) ? mel : MAXLEN;
    const int row0 = chunk * ROWS + wid * 8;     // this warp's first row

    // ---------- Phase 2: tokens for this warp's 8 rows (lanes 0-7) ---------
    int tok = 0, val = 0;
    if (lane < 8) {
        const int pos = row0 + lane;
        int lo = 0, hi = TT;
        while (lo < hi) {                        // searchsorted(cum,pos,'right')
            const int mid = (lo + hi) >> 1;
            if (s_cum[mid] <= pos) lo = mid + 1; else hi = mid;
        }
        tok = (lo > TT - 1) ? TT - 1 : lo;
        val = (pos < lim);
    }

    // ---------- Phase 3: direct gather, 4 pair-batches (6 loads in flight) --
    const float4* encb = enc + (size_t)b * TT * D4;
    float4*       dst  = out + (size_t)(b * MAXLEN + row0) * D4;
    const float4  z    = make_float4(0.f, 0.f, 0.f, 0.f);

    #pragma unroll
    for (int p = 0; p < 4; p++) {
        const int ta = __shfl_sync(FULL, tok, 2 * p);
        const int va = __shfl_sync(FULL, val, 2 * p);
        const int tb = __shfl_sync(FULL, tok, 2 * p + 1);
        const int vb = __shfl_sync(FULL, val, 2 * p + 1);

        const float4* sA = encb + (size_t)ta * D4;
        const float4* sB = encb + (size_t)tb * D4;
        float4 a0 = sA[lane], a1 = sA[lane + 32], a2 = sA[lane + 64];
        float4 b0 = sB[lane], b1 = sB[lane + 32], b2 = sB[lane + 64];

        float4* dp = dst + (size_t)(2 * p) * D4;
        dp[lane]            = va ? a0 : z;
        dp[lane + 32]       = va ? a1 : z;
        dp[lane + 64]       = va ? a2 : z;
        dp[D4 + lane]       = vb ? b0 : z;
        dp[D4 + lane + 32]  = vb ? b1 : z;
        dp[D4 + lane + 64]  = vb ? b2 : z;
    }

    if (write_mel && chunk == 0 && tid == 0) mel_out[b] = (float)mel;
}

extern "C" void kernel_launch(void* const* d_in, const int* in_sizes, int n_in,
                              void* d_out, int out_size) {
    const float4* enc = (const float4*)d_in[0];
    const int*    dur = (const int*)d_in[1];
    float*        out = (float*)d_out;

    const long long expanded_elems = (long long)BB * MAXLEN * DD;  // 25,165,824
    const int write_mel = (out_size > expanded_elems) ? 1 : 0;

    fused_kernel<<<BB * CHUNKS, NTHR>>>(dur, enc, (float4*)d_out,
                                        out + expanded_elems, write_mel);
}

// round 14
// speedup vs baseline: 1.0013x; 1.0013x over previous
#include <cuda_runtime.h>
#include <cuda_bf16.h>

#define BB 16
#define TT 512
#define DD 384
#define D4 96             // float4 per row
#define MAXLEN 4096
#define ROWS 64           // mel rows per block (8 per warp, 8 warps)
#define CHUNKS (MAXLEN / ROWS)   // 64
#define NTHR 256

__global__ void __launch_bounds__(NTHR, 8)
fused_kernel(const int* __restrict__ dur,
             const float4* __restrict__ enc,
             float4* __restrict__ out,
             float* __restrict__ mel_out, int write_mel)
{
    __shared__ int s_cum[TT];
    __shared__ int s_wsum[8];

    const int bidx  = blockIdx.x;
    const int b     = bidx >> 6;             // / CHUNKS
    const int chunk = bidx & (CHUNKS - 1);
    const int tid   = threadIdx.x;
    const int lane  = tid & 31;
    const int wid   = tid >> 5;
    const unsigned FULL = 0xffffffffu;

    // ---------- Phase 1: cumsum of 512 durations (2 per thread, int2) ------
    int2 d2 = ((const int2*)(dur + b * TT))[tid];
    int v = d2.x + d2.y;
    #pragma unroll
    for (int off = 1; off < 32; off <<= 1) {
        int n = __shfl_up_sync(FULL, v, off);
        if (lane >= off) v += n;
    }
    if (lane == 31) s_wsum[wid] = v;
    __syncthreads();
    if (wid == 0) {
        int w = (lane < 8) ? s_wsum[lane] : 0;
        #pragma unroll
        for (int off = 1; off < 8; off <<= 1) {
            int n = __shfl_up_sync(FULL, w, off);
            if (lane >= off) w += n;
        }
        if (lane < 8) s_wsum[lane] = w;
    }
    __syncthreads();
    const int base = (wid > 0) ? s_wsum[wid - 1] : 0;
    const int incl = v + base;
    s_cum[2 * tid]     = incl - d2.y;
    s_cum[2 * tid + 1] = incl;
    __syncthreads();

    const int mel  = s_cum[TT - 1];
    const int lim  = (mel < MAXLEN) ? mel : MAXLEN;
    const int row0 = chunk * ROWS + wid * 8;     // this warp's first row

    // ---------- Phase 2: tokens for this warp's 8 rows (lanes 0-7) ---------
    int tok = 0, val = 0;
    if (lane < 8) {
        const int pos = row0 + lane;
        int lo = 0, hi = TT;
        while (lo < hi) {                        // searchsorted(cum,pos,'right')
            const int mid = (lo + hi) >> 1;
            if (s_cum[mid] <= pos) lo = mid + 1; else hi = mid;
        }
        tok = (lo > TT - 1) ? TT - 1 : lo;
        val = (pos < lim);
    }

    // ---------- Phase 3: direct gather, 4 pair-batches (6 loads in flight) --
    const float4* encb = enc + (size_t)b * TT * D4;
    float4*       dst  = out + (size_t)(b * MAXLEN + row0) * D4;
    const float4  z    = make_float4(0.f, 0.f, 0.f, 0.f);

    #pragma unroll
    for (int p = 0; p < 4; p++) {
        const int ta = __shfl_sync(FULL, tok, 2 * p);
        const int va = __shfl_sync(FULL, val, 2 * p);
        const int tb = __shfl_sync(FULL, tok, 2 * p + 1);
        const int vb = __shfl_sync(FULL, val, 2 * p + 1);

        const float4* sA = encb + (size_t)ta * D4;
        const float4* sB = encb + (size_t)tb * D4;
        float4 a0 = sA[lane], a1 = sA[lane + 32], a2 = sA[lane + 64];
        float4 b0 = sB[lane], b1 = sB[lane + 32], b2 = sB[lane + 64];

        float4* dp = dst + (size_t)(2 * p) * D4;
        dp[lane]            = va ? a0 : z;
        dp[lane + 32]       = va ? a1 : z;
        dp[lane + 64]       = va ? a2 : z;
        dp[D4 + lane]       = vb ? b0 : z;
        dp[D4 + lane + 32]  = vb ? b1 : z;
        dp[D4 + lane + 64]  = vb ? b2 : z;
    }

    if (write_mel && chunk == 0 && tid == 0) mel_out[b] = (float)mel;
}

extern "C" void kernel_launch(void* const* d_in, const int* in_sizes, int n_in,
                              void* d_out, int out_size) {
    const float4* enc = (const float4*)d_in[0];
    const int*    dur = (const int*)d_in[1];
    float*        out = (float*)d_out;

    const long long expanded_elems = (long long)BB * MAXLEN * DD;  // 25,165,824
    const int write_mel = (out_size > expanded_elems) ? 1 : 0;

    fused_kernel<<<BB * CHUNKS, NTHR>>>(dur, enc, (float4*)d_out,
                                        out + expanded_elems, write_mel);
}